// round 4
// baseline (speedup 1.0000x reference)
#include <cuda_runtime.h>
#include <cuda_bf16.h>

#define NK    64
#define PLANE (256 * 64)
#define CH    (256 * 256 * 64)
#define NSEG  7
#define NBLK  (2 * 32 * NSEG)   // 448

__device__ double g_div_sum;
__device__ double g_smooth_sum;
__device__ float  g_sbin[2][63];
__device__ float  g_qbin[2][63];
__device__ unsigned g_done;

// 3 planes per stream: [0],[1] local (k=kk,kk+1), [2] = shuffled (k=kk+2)
struct Row {
    float zj[3], zp[3], bxj[3], bxp[3], byj[3], byp[3], sz[3];
};

__global__ void __launch_bounds__(256, 3) kFused(const float* __restrict__ zg,
                                                 const float* __restrict__ tg,
                                                 float* __restrict__ out) {
    const int tid  = threadIdx.x;
    const int lane = tid & 31;
    const int wid  = tid >> 5;          // warp = one j column
    const int kk   = 2 * lane;
    const unsigned FM = 0xffffffffu;

    int bid  = blockIdx.x;
    int jt   = bid & 31;
    int rest = bid >> 5;
    int seg  = rest % NSEG;
    int b    = rest / NSEG;
    int i0   = (seg * 256) / NSEG;
    int i1   = ((seg + 1) * 256) / NSEG;

    int j   = jt * 8 + wid;
    int jmc = (j > 0)   ? j - 1 : 0;
    int jpc = (j < 255) ? j + 1 : 255;
    bool jdiv = (j < 255);
    bool jsm  = (j >= 1 && j <= 254);
    bool l31  = (lane < 31);

    const float* zb = zg + (size_t)b * CH + kk;
    const float* xb = tg + (size_t)b * 3 * CH + kk;
    const float* yb = xb + CH;
    const float* wb = yb + CH;
    const int offj = j * NK, offm = jmc * NK, offp = jpc * NK;

    __shared__ float shS[63], shQ[63];
    for (int t = tid; t < 63; t += 256) { shS[t] = 0.f; shQ[t] = 0.f; }
    __syncthreads();

    Row R[2];
    #pragma unroll
    for (int t = 0; t < 3; t++) {
        R[0].zj[t] = R[0].zp[t] = R[0].bxj[t] = R[0].bxp[t] = 0.f;
        R[0].byj[t] = R[0].byp[t] = R[0].sz[t] = 0.f;
    }

    float d2c2_0 = 0.f, d2c2_1 = 0.f;
    float d2c1_0 = 0.f, d2c1_1 = 0.f;
    float d2l1_0 = 0.f, d2l1_1 = 0.f;
    float d2r1_0 = 0.f, d2r1_1 = 0.f;
    float d2p1 = 0.f, d2n1 = 0.f;
    float sS0 = 0.f, sS1 = 0.f, sQ0 = 0.f, sQ1 = 0.f;
    float accD = 0.f, accL = 0.f;

    const int iters = (i1 - i0) + 2;
    int gi = i0 - 1;
    #pragma unroll 1
    for (int it = 0; it < iters; it++, gi++) {
        Row& P = R[it & 1];
        Row& C = R[(it & 1) ^ 1];

        int gic = gi < 0 ? 0 : (gi > 255 ? 255 : gi);
        size_t ro = (size_t)gic * PLANE;

        float2 zmf = *(const float2*)(zb + ro + offm);
        float2 zjf = *(const float2*)(zb + ro + offj);
        float2 zpf = *(const float2*)(zb + ro + offp);
        float2 xjf = *(const float2*)(xb + ro + offj);
        float2 xpf = *(const float2*)(xb + ro + offp);
        float2 yjf = *(const float2*)(yb + ro + offj);
        float2 ypf = *(const float2*)(yb + ro + offp);
        float2 wjf = *(const float2*)(wb + ro + offj);
        float2 wpf = *(const float2*)(wb + ro + offp);

        float zm0 = zmf.x, zm1 = zmf.y;
        C.zj[0] = zjf.x; C.zj[1] = zjf.y;
        C.zp[0] = zpf.x; C.zp[1] = zpf.y;
        C.bxj[0] = xjf.x; C.bxj[1] = xjf.y;
        C.bxp[0] = xpf.x; C.bxp[1] = xpf.y;
        C.byj[0] = yjf.x; C.byj[1] = yjf.y;
        C.byp[0] = ypf.x; C.byp[1] = ypf.y;
        C.sz[0] = wjf.x + wpf.x; C.sz[1] = wjf.y + wpf.y;

        // k+2 boundary plane from next lane (lane 31 garbage, guarded off)
        float zm2 = __shfl_down_sync(FM, zm0, 1);
        C.zj[2]  = __shfl_down_sync(FM, C.zj[0], 1);
        C.zp[2]  = __shfl_down_sync(FM, C.zp[0], 1);
        C.bxj[2] = __shfl_down_sync(FM, C.bxj[0], 1);
        C.bxp[2] = __shfl_down_sync(FM, C.bxp[0], 1);
        C.byj[2] = __shfl_down_sync(FM, C.byj[0], 1);
        C.byp[2] = __shfl_down_sync(FM, C.byp[0], 1);
        C.sz[2]  = __shfl_down_sync(FM, C.sz[0], 1);

        // dz edges (this row, 3 columns)
        float ec0 = C.zj[1] - C.zj[0], ec1 = C.zj[2] - C.zj[1];
        float el0 = zm1 - zm0,         el1 = zm2 - zm1;
        float er0 = C.zp[1] - C.zp[0], er1 = C.zp[2] - C.zp[1];
        float d2c0_0 = ec0 * ec0, d2c0_1 = ec1 * ec1;
        float d2l0_0 = el0 * el0, d2l0_1 = el1 * el1;
        float d2r0_0 = er0 * er0, d2r0_1 = er1 * er1;
        float d2p0 = __shfl_up_sync(FM, d2c0_1, 1);
        float d2n0 = __shfl_down_sync(FM, d2c0_0, 1);

        bool ownC = (gi >= i0) && (gi < i1);
        // std accumulation (center column)
        if (ownC) {
            sS0 += ec0; sQ0 += ec0 * ec0;
            if (l31) { sS1 += ec1; sQ1 += ec1 * ec1; }
        }

        // div cell between rows P (gi-1) and C (gi)
        bool ownP = (gi - 1 >= i0) && (gi - 1 < i1) && (gi <= 255);
        if (ownP && jdiv) {
            float p0[3], p1[3], q0[3], q1[3], sl[3], Pl[3];
            #pragma unroll
            for (int t = 0; t < 3; t++) {
                p0[t] = P.bxj[t] + P.bxp[t];
                p1[t] = C.bxj[t] + C.bxp[t];
                q0[t] = P.byj[t] + C.byj[t];
                q1[t] = P.byp[t] + C.byp[t];
                sl[t] = P.sz[t] + C.sz[t];
                float A = P.zj[t] - C.zj[t];
                float B = P.zp[t] - C.zp[t];
                Pl[t] = (P.bxj[t] * A + P.bxp[t] * B + p1[t] * (A + B)
                       + (C.byj[t] + C.byp[t] + P.byp[t]) * (C.zj[t] - C.zp[t])
                       + (P.byj[t] + P.byp[t] + C.byp[t]) * (P.zj[t] - P.zp[t]))
                       * (1.f / 6.f);
            }
            // cell t=0 (always valid: k=kk<=62)
            {
                float d00 = fabsf(P.zj[1] - P.zj[0]);
                float d01 = fabsf(P.zp[1] - P.zp[0]);
                float d10 = fabsf(C.zj[1] - C.zj[0]);
                float d11 = fabsf(C.zp[1] - C.zp[0]);
                float A1 = (p1[0] + p1[1]) * (d10 + d11);
                float A2 = (p0[0] + p0[1]) * (d00 + d01);
                float A3 = (q1[0] + q1[1]) * (d01 + d11);
                float A4 = (q0[0] + q0[1]) * (d00 + d10);
                float num = 0.125f * ((A1 - A2) + (A3 - A4))
                          + 0.25f * (sl[1] - sl[0]) + (Pl[1] - Pl[0]);
                float sx  = (p0[0] + p1[0]) + (p0[1] + p1[1]);
                float sy  = (q0[0] + q1[0]) + (q0[1] + q1[1]);
                float sz2 = sl[0] + sl[1];
                float den = 0.015625f * (sx * sx + sy * sy + sz2 * sz2) + 1e-10f;
                accD += __fdividef(num * num, den);
            }
            // cell t=1 (k=kk+1, valid for lane<31)
            if (l31) {
                float d00 = fabsf(P.zj[2] - P.zj[1]);
                float d01 = fabsf(P.zp[2] - P.zp[1]);
                float d10 = fabsf(C.zj[2] - C.zj[1]);
                float d11 = fabsf(C.zp[2] - C.zp[1]);
                float A1 = (p1[1] + p1[2]) * (d10 + d11);
                float A2 = (p0[1] + p0[2]) * (d00 + d01);
                float A3 = (q1[1] + q1[2]) * (d01 + d11);
                float A4 = (q0[1] + q0[2]) * (d00 + d10);
                float num = 0.125f * ((A1 - A2) + (A3 - A4))
                          + 0.25f * (sl[2] - sl[1]) + (Pl[2] - Pl[1]);
                float sx  = (p0[1] + p1[1]) + (p0[2] + p1[2]);
                float sy  = (q0[1] + q1[1]) + (q0[2] + q1[2]);
                float sz2 = sl[1] + sl[2];
                float den = 0.015625f * (sx * sx + sy * sy + sz2 * sz2) + 1e-10f;
                accD += __fdividef(num * num, den);
            }
        }

        // smooth lap at center row ic = gi-1
        {
            int ic = gi - 1;
            if (ic >= i0 && ic < i1 && ic >= 1 && ic <= 254 && gi <= 255 && jsm) {
                // k = kk: needs lane>=1 (k>=1) and kk<=61 (lane<=30)
                if (lane >= 1 && lane <= 30) {
                    float lap = 6.f * d2c1_0 - d2c2_0 - d2c0_0
                              - d2l1_0 - d2r1_0 - d2p1 - d2c1_1;
                    accL += lap * lap;
                }
                // k = kk+1: needs kk+1<=61 (lane<=30)
                if (lane <= 30) {
                    float lap = 6.f * d2c1_1 - d2c2_1 - d2c0_1
                              - d2l1_1 - d2r1_1 - d2c1_0 - d2n1;
                    accL += lap * lap;
                }
            }
        }

        // rotate stencil history
        d2c2_0 = d2c1_0; d2c2_1 = d2c1_1;
        d2c1_0 = d2c0_0; d2c1_1 = d2c0_1;
        d2l1_0 = d2l0_0; d2l1_1 = d2l0_1;
        d2r1_0 = d2r0_0; d2r1_1 = d2r0_1;
        d2p1 = d2p0; d2n1 = d2n0;
    }

    // std bins: thread partials -> shared -> global
    atomicAdd(&shS[kk], sS0);
    atomicAdd(&shQ[kk], sQ0);
    if (l31) {
        atomicAdd(&shS[kk + 1], sS1);
        atomicAdd(&shQ[kk + 1], sQ1);
    }
    __syncthreads();
    for (int t = tid; t < 63; t += 256) {
        atomicAdd(&g_sbin[b][t], shS[t]);
        atomicAdd(&g_qbin[b][t], shQ[t]);
    }

    // block reduce accD, accL
    {
        __shared__ float sa[8], sb2[8];
        #pragma unroll
        for (int o = 16; o > 0; o >>= 1) {
            accD += __shfl_down_sync(FM, accD, o);
            accL += __shfl_down_sync(FM, accL, o);
        }
        if (lane == 0) { sa[wid] = accD; sb2[wid] = accL; }
        __syncthreads();
        if (tid == 0) {
            float tD = 0.f, tL = 0.f;
            #pragma unroll
            for (int q = 0; q < 8; q++) { tD += sa[q]; tL += sb2[q]; }
            atomicAdd(&g_div_sum, (double)tD);
            atomicAdd(&g_smooth_sum, (double)tL);
        }
    }

    // last-block finalize
    __threadfence();
    __shared__ bool islast;
    if (tid == 0) {
        unsigned v = atomicAdd(&g_done, 1u);
        islast = (v == gridDim.x - 1);
    }
    __syncthreads();
    if (islast) {
        if (tid == 0) g_done = 0;
        float v = 0.f;
        if (tid < 126) {
            float S = ((float*)g_sbin)[tid];
            float Q = ((float*)g_qbin)[tid];
            float var = (Q - S * S * (1.0f / 65536.0f)) * (1.0f / 65535.0f);
            v = sqrtf(fmaxf(var, 0.f));
        }
        __shared__ float sf[8];
        #pragma unroll
        for (int o = 16; o > 0; o >>= 1) v += __shfl_down_sync(FM, v, o);
        if (lane == 0) sf[wid] = v;
        __syncthreads();
        if (tid == 0) {
            float tot = 0.f;
            #pragma unroll
            for (int q = 0; q < 8; q++) tot += sf[q];
            double lstd = (double)(tot / 126.f);
            out[0] = (float)(g_div_sum * (1.0e9 / 8193150.0));
            out[1] = (float)(g_smooth_sum * (10.0 / 7870952.0) + lstd * 100.0);
        }
    }
}

__global__ void kZ_zero() {
    int t = threadIdx.x;
    if (t == 0) { g_div_sum = 0.0; g_smooth_sum = 0.0; g_done = 0u; }
    if (t < 126) { ((float*)g_sbin)[t] = 0.f; ((float*)g_qbin)[t] = 0.f; }
}

extern "C" void kernel_launch(void* const* d_in, const int* in_sizes, int n_in,
                              void* d_out, int out_size) {
    const float* outp = (const float*)d_in[0];
    const float* tgt  = (const float*)d_in[1];
    if (n_in >= 2 && in_sizes[0] > in_sizes[1]) {
        const float* tmp = outp; outp = tgt; tgt = tmp;
    }
    float* out = (float*)d_out;

    kZ_zero<<<1, 128>>>();
    kFused<<<NBLK, 256>>>(outp, tgt, out);
}

// round 5
// speedup vs baseline: 1.2569x; 1.2569x over previous
#include <cuda_runtime.h>
#include <cuda_bf16.h>

#define NK    64
#define PLANE (256 * 64)
#define CH    (256 * 256 * 64)
#define NSEG  9
#define NBLK  (2 * 16 * NSEG)   // 288

__device__ double g_div_sum;
__device__ double g_smooth_sum;
__device__ float  g_sbin[2][63];
__device__ float  g_qbin[2][63];
__device__ unsigned g_done;

struct Row {
    float bxj[4], bxp[4], byj[4], byp[4], szr[4];
    float bxjS, bxpS, byjS, bypS, szrS;
    float zj[5], zp[5];
};

__device__ __forceinline__ void cp16(void* sdst, const void* gsrc) {
    unsigned s = (unsigned)__cvta_generic_to_shared(sdst);
    asm volatile("cp.async.cg.shared.global [%0], [%1], 16;\n" :: "r"(s), "l"(gsrc));
}
#define CP_COMMIT() asm volatile("cp.async.commit_group;\n" ::: "memory")
#define CP_WAIT1()  asm volatile("cp.async.wait_group 1;\n" ::: "memory")

// Copy one i-row tile into smem buffer: z (18 cols incl j-halo) + x,y,w (17 cols).
__device__ __forceinline__ void cp_row(int tid, int j0,
                                       const float* __restrict__ zr,
                                       const float* __restrict__ tr,
                                       float* smZ, float* smT) {
    #pragma unroll
    for (int u = 0; u < 5; u++) {
        int idx = tid + u * 256;
        if (idx < 1104) {
            if (idx < 288) {
                int c = idx >> 4, f = idx & 15;
                int gj = j0 - 1 + c; gj = gj < 0 ? 0 : (gj > 255 ? 255 : gj);
                cp16(smZ + c * NK + f * 4, zr + gj * NK + f * 4);
            } else {
                int t = idx - 288;
                int s = (t < 272) ? 0 : ((t < 544) ? 1 : 2);
                int r = t - s * 272;
                int c = r >> 4, f = r & 15;
                int gj = j0 + c; gj = gj > 255 ? 255 : gj;
                cp16(smT + s * 1088 + c * NK + f * 4,
                     tr + (size_t)s * CH + gj * NK + f * 4);
            }
        }
    }
}

// One row-step: loads from smem buffer, math identical to the R2 kernel.
__device__ __forceinline__ void stepS(
    Row& P, Row& C, int gi, int i0, int i1, bool jdiv, bool jsm,
    int col, int k4, int kk,
    const float* smZ, const float* smT,
    float d2C2[4], float d2C1[4], float& d2p1, float& d2n1,
    float d2L1[4], float d2R1[4],
    float sS[4], float sQ[4], float& accD, float& accL)
{
    const unsigned FM = 0xffffffffu;
    const float4* Z4 = (const float4*)smZ;
    const float4* X4 = (const float4*)smT;
    const float4* Y4 = (const float4*)(smT + 1088);
    const float4* W4 = (const float4*)(smT + 2176);

    float4 zjm = Z4[col * 16 + k4];
    float4 zjf = Z4[(col + 1) * 16 + k4];
    float4 zjp = Z4[(col + 2) * 16 + k4];
    float4 xjf = X4[col * 16 + k4];
    float4 xjp = X4[(col + 1) * 16 + k4];
    float4 yjf = Y4[col * 16 + k4];
    float4 yjp = Y4[(col + 1) * 16 + k4];
    float4 wjf = W4[col * 16 + k4];
    float4 wjp = W4[(col + 1) * 16 + k4];

    float zm[5];
    zm[0] = zjm.x; zm[1] = zjm.y; zm[2] = zjm.z; zm[3] = zjm.w;
    C.zj[0] = zjf.x; C.zj[1] = zjf.y; C.zj[2] = zjf.z; C.zj[3] = zjf.w;
    C.zp[0] = zjp.x; C.zp[1] = zjp.y; C.zp[2] = zjp.z; C.zp[3] = zjp.w;
    C.bxj[0] = xjf.x; C.bxj[1] = xjf.y; C.bxj[2] = xjf.z; C.bxj[3] = xjf.w;
    C.bxp[0] = xjp.x; C.bxp[1] = xjp.y; C.bxp[2] = xjp.z; C.bxp[3] = xjp.w;
    C.byj[0] = yjf.x; C.byj[1] = yjf.y; C.byj[2] = yjf.z; C.byj[3] = yjf.w;
    C.byp[0] = yjp.x; C.byp[1] = yjp.y; C.byp[2] = yjp.z; C.byp[3] = yjp.w;
    C.szr[0] = wjf.x + wjp.x; C.szr[1] = wjf.y + wjp.y;
    C.szr[2] = wjf.z + wjp.z; C.szr[3] = wjf.w + wjp.w;

    zm[4]   = __shfl_down_sync(FM, zm[0],    1, 16);
    C.zj[4] = __shfl_down_sync(FM, C.zj[0],  1, 16);
    C.zp[4] = __shfl_down_sync(FM, C.zp[0],  1, 16);
    C.bxjS  = __shfl_down_sync(FM, C.bxj[0], 1, 16);
    C.bxpS  = __shfl_down_sync(FM, C.bxp[0], 1, 16);
    C.byjS  = __shfl_down_sync(FM, C.byj[0], 1, 16);
    C.bypS  = __shfl_down_sync(FM, C.byp[0], 1, 16);
    C.szrS  = __shfl_down_sync(FM, C.szr[0], 1, 16);

    float d2C0[4], d2L0[4], d2R0[4];
    #pragma unroll
    for (int t = 0; t < 4; t++) {
        float dc = C.zj[t + 1] - C.zj[t]; d2C0[t] = dc * dc;
        float dl = zm[t + 1]   - zm[t];   d2L0[t] = dl * dl;
        float dr = C.zp[t + 1] - C.zp[t]; d2R0[t] = dr * dr;
    }
    float d2p0 = __shfl_up_sync(FM, d2C0[3], 1, 16);
    float d2n0 = __shfl_down_sync(FM, d2C0[0], 1, 16);

    if (gi >= i0 && gi < i1) {
        #pragma unroll
        for (int t = 0; t < 4; t++) if (kk + t < 63) {
            float d = C.zj[t + 1] - C.zj[t];
            sS[t] += d; sQ[t] += d * d;
        }
    }

    if (gi - 1 >= i0 && gi - 1 < i1 && gi <= 255 && jdiv) {
        float p0l[5], p1l[5], q0l[5], q1l[5], szl[5], Pl[5];
        #pragma unroll
        for (int t = 0; t < 5; t++) {
            float pbxj = (t < 4) ? P.bxj[t] : P.bxjS;
            float pbxp = (t < 4) ? P.bxp[t] : P.bxpS;
            float pbyj = (t < 4) ? P.byj[t] : P.byjS;
            float pbyp = (t < 4) ? P.byp[t] : P.bypS;
            float psz  = (t < 4) ? P.szr[t] : P.szrS;
            float cbxj = (t < 4) ? C.bxj[t] : C.bxjS;
            float cbxp = (t < 4) ? C.bxp[t] : C.bxpS;
            float cbyj = (t < 4) ? C.byj[t] : C.byjS;
            float cbyp = (t < 4) ? C.byp[t] : C.bypS;
            float csz  = (t < 4) ? C.szr[t] : C.szrS;
            float pzj = P.zj[t], pzp = P.zp[t];
            float czj = C.zj[t], czp = C.zp[t];
            p0l[t] = pbxj + pbxp;
            p1l[t] = cbxj + cbxp;
            q0l[t] = pbyj + cbyj;
            q1l[t] = pbyp + cbyp;
            szl[t] = psz + csz;
            Pl[t] = ((pbxj + cbxj + cbxp) * (pzj - czj)
                   + (pbxp + cbxp + cbxj) * (pzp - czp)
                   + (cbyj + cbyp + pbyp) * (czj - czp)
                   + (pbyj + pbyp + cbyp) * (pzj - pzp)) * (1.f / 6.f);
        }
        #pragma unroll
        for (int t = 0; t < 4; t++) if (kk + t < 63) {
            float d00 = fabsf(P.zj[t + 1] - P.zj[t]);
            float d01 = fabsf(P.zp[t + 1] - P.zp[t]);
            float d10 = fabsf(C.zj[t + 1] - C.zj[t]);
            float d11 = fabsf(C.zp[t + 1] - C.zp[t]);
            float A1 = (p1l[t] + p1l[t + 1]) * (d10 + d11);
            float A2 = (p0l[t] + p0l[t + 1]) * (d00 + d01);
            float A3 = (q1l[t] + q1l[t + 1]) * (d01 + d11);
            float A4 = (q0l[t] + q0l[t + 1]) * (d00 + d10);
            float num = 0.125f * ((A1 - A2) + (A3 - A4))
                      + 0.25f * (szl[t + 1] - szl[t])
                      + (Pl[t + 1] - Pl[t]);
            float sx  = (p0l[t] + p1l[t]) + (p0l[t + 1] + p1l[t + 1]);
            float sy  = (q0l[t] + q1l[t]) + (q0l[t + 1] + q1l[t + 1]);
            float szz = szl[t] + szl[t + 1];
            float den = 0.015625f * (sx * sx + sy * sy + szz * szz) + 1e-10f;
            accD += __fdividef(num * num, den);
        }
    }

    int ic = gi - 1;
    if (ic >= i0 && ic < i1 && ic >= 1 && ic <= 254 && gi <= 255 && jsm) {
        #pragma unroll
        for (int t = 0; t < 4; t++) {
            int k = kk + t;
            if (k >= 1 && k <= 61) {
                float km = (t > 0) ? d2C1[t - 1] : d2p1;
                float kp = (t < 3) ? d2C1[t + 1] : d2n1;
                float lap = 6.f * d2C1[t] - d2C2[t] - d2C0[t]
                          - d2L1[t] - d2R1[t] - km - kp;
                accL += lap * lap;
            }
        }
    }

    #pragma unroll
    for (int t = 0; t < 4; t++) {
        d2C2[t] = d2C1[t]; d2C1[t] = d2C0[t];
        d2L1[t] = d2L0[t]; d2R1[t] = d2R0[t];
    }
    d2p1 = d2p0; d2n1 = d2n0;
}

__global__ void __launch_bounds__(256, 2) kFused(const float* __restrict__ zg,
                                                 const float* __restrict__ tg,
                                                 float* __restrict__ out) {
    const int tid = threadIdx.x;
    const int k4  = tid & 15;
    const int col = tid >> 4;
    const int kk  = 4 * k4;

    int bid  = blockIdx.x;
    int jt   = bid & 15;
    int rest = bid >> 4;
    int seg  = rest % NSEG;
    int b    = rest / NSEG;
    int i0   = (seg * 256) / NSEG;
    int i1   = ((seg + 1) * 256) / NSEG;

    int j = jt * 16 + col;
    bool jdiv = (j < 255);
    bool jsm  = (j >= 1 && j <= 254);

    const float* zbase = zg + (size_t)b * CH;
    const float* tbase = tg + (size_t)b * 3 * CH;

    __shared__ alignas(16) float smZ[2][18 * NK];
    __shared__ alignas(16) float smT[2][3 * 1088];
    __shared__ float shS[63], shQ[63];
    for (int t = tid; t < 63; t += 256) { shS[t] = 0.f; shQ[t] = 0.f; }

    Row RA, RB;
    #pragma unroll
    for (int t = 0; t < 5; t++) { RA.zj[t] = 0.f; RA.zp[t] = 0.f; }
    #pragma unroll
    for (int t = 0; t < 4; t++) {
        RA.bxj[t] = RA.bxp[t] = RA.byj[t] = RA.byp[t] = RA.szr[t] = 0.f;
    }
    RA.bxjS = RA.bxpS = RA.byjS = RA.bypS = RA.szrS = 0.f;

    float d2C2[4] = {0,0,0,0}, d2C1[4] = {0,0,0,0};
    float d2L1[4] = {0,0,0,0}, d2R1[4] = {0,0,0,0};
    float d2p1 = 0.f, d2n1 = 0.f;
    float sS[4] = {0,0,0,0}, sQ[4] = {0,0,0,0};
    float accD = 0.f, accL = 0.f;

    const int j0 = jt * 16;
    const int iters = (i1 - i0) + 2;
    int gi = i0 - 1;

    // preload row i0-1 into buf 0
    {
        int gic = gi < 0 ? 0 : gi;
        cp_row(tid, j0, zbase + (size_t)gic * PLANE, tbase + (size_t)gic * PLANE,
               smZ[0], smT[0]);
        CP_COMMIT();
    }

    #pragma unroll 1
    for (int it = 0; it < iters; it += 2) {
        // sub-step A: compute buf 0 (row gi), prefetch row gi+1 -> buf 1
        {
            int gn = gi + 1; gn = gn > 255 ? 255 : gn;
            cp_row(tid, j0, zbase + (size_t)gn * PLANE, tbase + (size_t)gn * PLANE,
                   smZ[1], smT[1]);
            CP_COMMIT();
            CP_WAIT1();
            __syncthreads();
            stepS(RA, RB, gi, i0, i1, jdiv, jsm, col, k4, kk, smZ[0], smT[0],
                  d2C2, d2C1, d2p1, d2n1, d2L1, d2R1, sS, sQ, accD, accL);
            gi++;
            __syncthreads();
        }
        // sub-step B: compute buf 1 (row gi), prefetch row gi+1 -> buf 0
        if (it + 1 < iters) {
            int gn = gi + 1; gn = gn > 255 ? 255 : gn;
            cp_row(tid, j0, zbase + (size_t)gn * PLANE, tbase + (size_t)gn * PLANE,
                   smZ[0], smT[0]);
            CP_COMMIT();
            CP_WAIT1();
            __syncthreads();
            stepS(RB, RA, gi, i0, i1, jdiv, jsm, col, k4, kk, smZ[1], smT[1],
                  d2C2, d2C1, d2p1, d2n1, d2L1, d2R1, sS, sQ, accD, accL);
            gi++;
            __syncthreads();
        }
    }

    // std bins: thread partials -> shared -> global
    #pragma unroll
    for (int t = 0; t < 4; t++) if (kk + t < 63) {
        atomicAdd(&shS[kk + t], sS[t]);
        atomicAdd(&shQ[kk + t], sQ[t]);
    }
    __syncthreads();
    for (int t = tid; t < 63; t += 256) {
        atomicAdd(&g_sbin[b][t], shS[t]);
        atomicAdd(&g_qbin[b][t], shQ[t]);
    }

    // block reduce accD, accL
    {
        __shared__ float sa[8], sb2[8];
        const unsigned FM = 0xffffffffu;
        #pragma unroll
        for (int o = 16; o > 0; o >>= 1) {
            accD += __shfl_down_sync(FM, accD, o);
            accL += __shfl_down_sync(FM, accL, o);
        }
        int w = tid >> 5;
        if ((tid & 31) == 0) { sa[w] = accD; sb2[w] = accL; }
        __syncthreads();
        if (tid == 0) {
            float tD = 0.f, tL = 0.f;
            #pragma unroll
            for (int q = 0; q < 8; q++) { tD += sa[q]; tL += sb2[q]; }
            atomicAdd(&g_div_sum, (double)tD);
            atomicAdd(&g_smooth_sum, (double)tL);
        }
    }

    // last-block finalize
    __threadfence();
    __shared__ bool islast;
    if (tid == 0) {
        unsigned v = atomicAdd(&g_done, 1u);
        islast = (v == gridDim.x - 1);
    }
    __syncthreads();
    if (islast) {
        if (tid == 0) g_done = 0;
        float v = 0.f;
        if (tid < 126) {
            float S = ((float*)g_sbin)[tid];
            float Q = ((float*)g_qbin)[tid];
            float var = (Q - S * S * (1.0f / 65536.0f)) * (1.0f / 65535.0f);
            v = sqrtf(fmaxf(var, 0.f));
        }
        __shared__ float sf[8];
        const unsigned FM = 0xffffffffu;
        #pragma unroll
        for (int o = 16; o > 0; o >>= 1) v += __shfl_down_sync(FM, v, o);
        if ((tid & 31) == 0) sf[tid >> 5] = v;
        __syncthreads();
        if (tid == 0) {
            float tot = 0.f;
            #pragma unroll
            for (int q = 0; q < 8; q++) tot += sf[q];
            double lstd = (double)(tot / 126.f);
            out[0] = (float)(g_div_sum * (1.0e9 / 8193150.0));
            out[1] = (float)(g_smooth_sum * (10.0 / 7870952.0) + lstd * 100.0);
        }
    }
}

__global__ void kZ_zero() {
    int t = threadIdx.x;
    if (t == 0) { g_div_sum = 0.0; g_smooth_sum = 0.0; g_done = 0u; }
    if (t < 126) { ((float*)g_sbin)[t] = 0.f; ((float*)g_qbin)[t] = 0.f; }
}

extern "C" void kernel_launch(void* const* d_in, const int* in_sizes, int n_in,
                              void* d_out, int out_size) {
    const float* outp = (const float*)d_in[0];
    const float* tgt  = (const float*)d_in[1];
    if (n_in >= 2 && in_sizes[0] > in_sizes[1]) {
        const float* tmp = outp; outp = tgt; tgt = tmp;
    }
    float* out = (float*)d_out;

    kZ_zero<<<1, 128>>>();
    kFused<<<NBLK, 256>>>(outp, tgt, out);
}

// round 7
// speedup vs baseline: 1.4740x; 1.1727x over previous
#include <cuda_runtime.h>
#include <cuda_bf16.h>

#define NK    64
#define PLANE (256 * 64)
#define CH    (256 * 256 * 64)
#define NSEG  9
#define NBLK  (2 * 16 * NSEG)   // 288

__device__ double g_div_sum;
__device__ double g_smooth_sum;
__device__ float  g_sbin[2][63];
__device__ float  g_qbin[2][63];
__device__ unsigned g_done;

#define ARR4(v) { (v).x, (v).y, (v).z, (v).w }

__device__ __forceinline__ void pf_l2(const void* p) {
    asm volatile("prefetch.global.L2 [%0];" :: "l"(p));
}

struct Row {
    float bxj[4], bxp[4], byj[4], byp[4], szr[4];
    float bxjS, bxpS, byjS, bypS, szrS;
    float zj[5], zp[5];
};

__device__ __forceinline__ void step(
    Row& P, Row& C, int gi, int gnext, int i0, int i1, bool jdiv, bool jsm,
    bool pfl, int kk,
    const float* __restrict__ zb, const float* __restrict__ xb,
    const float* __restrict__ yb, const float* __restrict__ wb,
    size_t offj, size_t offm, size_t offp,
    float d2C2[4], float d2C1[4], float& d2p1, float& d2n1,
    float d2L1[4], float d2R1[4],
    float sS[4], float sQ[4], float& accD, float& accL)
{
    const unsigned FM = 0xffffffffu;
    int gic = gi < 0 ? 0 : (gi > 255 ? 255 : gi);
    size_t ro = (size_t)gic * PLANE;

    float4 z00f = *(const float4*)(zb + ro + offm);
    float4 zjf  = *(const float4*)(zb + ro + offj);
    float4 zpf  = *(const float4*)(zb + ro + offp);
    float4 xjf  = *(const float4*)(xb + ro + offj);
    float4 xpf  = *(const float4*)(xb + ro + offp);
    float4 yjf  = *(const float4*)(yb + ro + offj);
    float4 ypf  = *(const float4*)(yb + ro + offp);
    float4 wjf  = *(const float4*)(wb + ro + offj);
    float4 wpf  = *(const float4*)(wb + ro + offp);

    // L2 prefetch of next row's 9 streams (1 lane per 128B line)
    {
        int gn = gnext > 255 ? 255 : gnext;
        size_t rn = (size_t)gn * PLANE;
        if (pfl) {
            pf_l2(zb + rn + offm); pf_l2(zb + rn + offj); pf_l2(zb + rn + offp);
            pf_l2(xb + rn + offj); pf_l2(xb + rn + offp);
            pf_l2(yb + rn + offj); pf_l2(yb + rn + offp);
            pf_l2(wb + rn + offj); pf_l2(wb + rn + offp);
        }
    }

    float zm[5];
    zm[0] = z00f.x; zm[1] = z00f.y; zm[2] = z00f.z; zm[3] = z00f.w;
    C.zj[0] = zjf.x; C.zj[1] = zjf.y; C.zj[2] = zjf.z; C.zj[3] = zjf.w;
    C.zp[0] = zpf.x; C.zp[1] = zpf.y; C.zp[2] = zpf.z; C.zp[3] = zpf.w;
    C.bxj[0] = xjf.x; C.bxj[1] = xjf.y; C.bxj[2] = xjf.z; C.bxj[3] = xjf.w;
    C.bxp[0] = xpf.x; C.bxp[1] = xpf.y; C.bxp[2] = xpf.z; C.bxp[3] = xpf.w;
    C.byj[0] = yjf.x; C.byj[1] = yjf.y; C.byj[2] = yjf.z; C.byj[3] = yjf.w;
    C.byp[0] = ypf.x; C.byp[1] = ypf.y; C.byp[2] = ypf.z; C.byp[3] = ypf.w;
    C.szr[0] = wjf.x + wpf.x; C.szr[1] = wjf.y + wpf.y;
    C.szr[2] = wjf.z + wpf.z; C.szr[3] = wjf.w + wpf.w;

    zm[4]   = __shfl_down_sync(FM, zm[0],    1, 16);
    C.zj[4] = __shfl_down_sync(FM, C.zj[0],  1, 16);
    C.zp[4] = __shfl_down_sync(FM, C.zp[0],  1, 16);
    C.bxjS  = __shfl_down_sync(FM, C.bxj[0], 1, 16);
    C.bxpS  = __shfl_down_sync(FM, C.bxp[0], 1, 16);
    C.byjS  = __shfl_down_sync(FM, C.byj[0], 1, 16);
    C.bypS  = __shfl_down_sync(FM, C.byp[0], 1, 16);
    C.szrS  = __shfl_down_sync(FM, C.szr[0], 1, 16);

    float d2C0[4], d2L0[4], d2R0[4];
    #pragma unroll
    for (int t = 0; t < 4; t++) {
        float dc = C.zj[t + 1] - C.zj[t]; d2C0[t] = dc * dc;
        float dl = zm[t + 1]   - zm[t];   d2L0[t] = dl * dl;
        float dr = C.zp[t + 1] - C.zp[t]; d2R0[t] = dr * dr;
    }
    float d2p0 = __shfl_up_sync(FM, d2C0[3], 1, 16);
    float d2n0 = __shfl_down_sync(FM, d2C0[0], 1, 16);

    if (gi >= i0 && gi < i1) {
        #pragma unroll
        for (int t = 0; t < 4; t++) if (kk + t < 63) {
            float d = C.zj[t + 1] - C.zj[t];
            sS[t] += d; sQ[t] += d * d;
        }
    }

    if (gi - 1 >= i0 && gi - 1 < i1 && gi <= 255 && jdiv) {
        float p0l[5], p1l[5], q0l[5], q1l[5], szl[5], Pl[5];
        #pragma unroll
        for (int t = 0; t < 5; t++) {
            float pbxj = (t < 4) ? P.bxj[t] : P.bxjS;
            float pbxp = (t < 4) ? P.bxp[t] : P.bxpS;
            float pbyj = (t < 4) ? P.byj[t] : P.byjS;
            float pbyp = (t < 4) ? P.byp[t] : P.bypS;
            float psz  = (t < 4) ? P.szr[t] : P.szrS;
            float cbxj = (t < 4) ? C.bxj[t] : C.bxjS;
            float cbxp = (t < 4) ? C.bxp[t] : C.bxpS;
            float cbyj = (t < 4) ? C.byj[t] : C.byjS;
            float cbyp = (t < 4) ? C.byp[t] : C.bypS;
            float csz  = (t < 4) ? C.szr[t] : C.szrS;
            float pzj = P.zj[t], pzp = P.zp[t];
            float czj = C.zj[t], czp = C.zp[t];
            p0l[t] = pbxj + pbxp;
            p1l[t] = cbxj + cbxp;
            q0l[t] = pbyj + cbyj;
            q1l[t] = pbyp + cbyp;
            szl[t] = psz + csz;
            Pl[t] = ((pbxj + cbxj + cbxp) * (pzj - czj)
                   + (pbxp + cbxp + cbxj) * (pzp - czp)
                   + (cbyj + cbyp + pbyp) * (czj - czp)
                   + (pbyj + pbyp + cbyp) * (pzj - pzp)) * (1.f / 6.f);
        }
        #pragma unroll
        for (int t = 0; t < 4; t++) if (kk + t < 63) {
            float d00 = fabsf(P.zj[t + 1] - P.zj[t]);
            float d01 = fabsf(P.zp[t + 1] - P.zp[t]);
            float d10 = fabsf(C.zj[t + 1] - C.zj[t]);
            float d11 = fabsf(C.zp[t + 1] - C.zp[t]);
            float A1 = (p1l[t] + p1l[t + 1]) * (d10 + d11);
            float A2 = (p0l[t] + p0l[t + 1]) * (d00 + d01);
            float A3 = (q1l[t] + q1l[t + 1]) * (d01 + d11);
            float A4 = (q0l[t] + q0l[t + 1]) * (d00 + d10);
            float num = 0.125f * ((A1 - A2) + (A3 - A4))
                      + 0.25f * (szl[t + 1] - szl[t])
                      + (Pl[t + 1] - Pl[t]);
            float sx  = (p0l[t] + p1l[t]) + (p0l[t + 1] + p1l[t + 1]);
            float sy  = (q0l[t] + q1l[t]) + (q0l[t + 1] + q1l[t + 1]);
            float szz = szl[t] + szl[t + 1];
            float den = 0.015625f * (sx * sx + sy * sy + szz * szz) + 1e-10f;
            accD += __fdividef(num * num, den);
        }
    }

    int ic = gi - 1;
    if (ic >= i0 && ic < i1 && ic >= 1 && ic <= 254 && gi <= 255 && jsm) {
        #pragma unroll
        for (int t = 0; t < 4; t++) {
            int k = kk + t;
            if (k >= 1 && k <= 61) {
                float km = (t > 0) ? d2C1[t - 1] : d2p1;
                float kp = (t < 3) ? d2C1[t + 1] : d2n1;
                float lap = 6.f * d2C1[t] - d2C2[t] - d2C0[t]
                          - d2L1[t] - d2R1[t] - km - kp;
                accL += lap * lap;
            }
        }
    }

    #pragma unroll
    for (int t = 0; t < 4; t++) {
        d2C2[t] = d2C1[t]; d2C1[t] = d2C0[t];
        d2L1[t] = d2L0[t]; d2R1[t] = d2R0[t];
    }
    d2p1 = d2p0; d2n1 = d2n0;
}

__global__ void __launch_bounds__(256, 2) kFused(const float* __restrict__ zg,
                                                 const float* __restrict__ tg,
                                                 float* __restrict__ out) {
    const int tid = threadIdx.x;
    const int k4  = tid & 15;
    const int col = tid >> 4;
    const int kk  = 4 * k4;

    int bid  = blockIdx.x;
    int jt   = bid & 15;
    int rest = bid >> 4;
    int seg  = rest % NSEG;
    int b    = rest / NSEG;
    int i0   = (seg * 256) / NSEG;
    int i1   = ((seg + 1) * 256) / NSEG;

    int j   = jt * 16 + col;
    int jmc = (j > 0)   ? j - 1 : 0;
    int jpc = (j < 255) ? j + 1 : 255;
    bool jdiv = (j < 255);
    bool jsm  = (j >= 1 && j <= 254);
    bool pfl  = ((k4 & 7) == 0);

    const float* zb = zg + (size_t)b * CH + kk;
    const float* xb = tg + (size_t)b * 3 * CH + kk;
    const float* yb = xb + CH;
    const float* wb = yb + CH;
    size_t offj = (size_t)j * NK, offm = (size_t)jmc * NK, offp = (size_t)jpc * NK;

    __shared__ float shS[63], shQ[63];
    for (int t = tid; t < 63; t += 256) { shS[t] = 0.f; shQ[t] = 0.f; }
    __syncthreads();

    Row RA, RB;
    #pragma unroll
    for (int t = 0; t < 5; t++) { RA.zj[t] = 0.f; RA.zp[t] = 0.f; }
    #pragma unroll
    for (int t = 0; t < 4; t++) {
        RA.bxj[t] = RA.bxp[t] = RA.byj[t] = RA.byp[t] = RA.szr[t] = 0.f;
    }
    RA.bxjS = RA.bxpS = RA.byjS = RA.bypS = RA.szrS = 0.f;

    float d2C2[4] = {0,0,0,0}, d2C1[4] = {0,0,0,0};
    float d2L1[4] = {0,0,0,0}, d2R1[4] = {0,0,0,0};
    float d2p1 = 0.f, d2n1 = 0.f;
    float sS[4] = {0,0,0,0}, sQ[4] = {0,0,0,0};
    float accD = 0.f, accL = 0.f;

    int iters = (i1 - i0) + 2;
    int gi = i0 - 1;
    for (int it = 0; it < iters; it += 2) {
        step(RA, RB, gi, gi + 1, i0, i1, jdiv, jsm, pfl, kk, zb, xb, yb, wb,
             offj, offm, offp, d2C2, d2C1, d2p1, d2n1, d2L1, d2R1,
             sS, sQ, accD, accL);
        gi++;
        if (it + 1 < iters) {
            step(RB, RA, gi, gi + 1, i0, i1, jdiv, jsm, pfl, kk, zb, xb, yb, wb,
                 offj, offm, offp, d2C2, d2C1, d2p1, d2n1, d2L1, d2R1,
                 sS, sQ, accD, accL);
            gi++;
        }
    }

    // std bins: thread partials -> shared -> global
    #pragma unroll
    for (int t = 0; t < 4; t++) if (kk + t < 63) {
        atomicAdd(&shS[kk + t], sS[t]);
        atomicAdd(&shQ[kk + t], sQ[t]);
    }
    __syncthreads();
    for (int t = tid; t < 63; t += 256) {
        atomicAdd(&g_sbin[b][t], shS[t]);
        atomicAdd(&g_qbin[b][t], shQ[t]);
    }

    // block reduce accD, accL
    {
        __shared__ float sa[8], sb2[8];
        const unsigned FM = 0xffffffffu;
        #pragma unroll
        for (int o = 16; o > 0; o >>= 1) {
            accD += __shfl_down_sync(FM, accD, o);
            accL += __shfl_down_sync(FM, accL, o);
        }
        int w = tid >> 5;
        if ((tid & 31) == 0) { sa[w] = accD; sb2[w] = accL; }
        __syncthreads();
        if (tid == 0) {
            float tD = 0.f, tL = 0.f;
            #pragma unroll
            for (int q = 0; q < 8; q++) { tD += sa[q]; tL += sb2[q]; }
            atomicAdd(&g_div_sum, (double)tD);
            atomicAdd(&g_smooth_sum, (double)tL);
        }
    }

    // last-block finalize
    __threadfence();
    __shared__ bool islast;
    if (tid == 0) {
        unsigned v = atomicAdd(&g_done, 1u);
        islast = (v == gridDim.x - 1);
    }
    __syncthreads();
    if (islast) {
        if (tid == 0) g_done = 0;
        float v = 0.f;
        if (tid < 126) {
            float S = ((float*)g_sbin)[tid];
            float Q = ((float*)g_qbin)[tid];
            float var = (Q - S * S * (1.0f / 65536.0f)) * (1.0f / 65535.0f);
            v = sqrtf(fmaxf(var, 0.f));
        }
        __shared__ float sf[8];
        const unsigned FM = 0xffffffffu;
        #pragma unroll
        for (int o = 16; o > 0; o >>= 1) v += __shfl_down_sync(FM, v, o);
        if ((tid & 31) == 0) sf[tid >> 5] = v;
        __syncthreads();
        if (tid == 0) {
            float tot = 0.f;
            #pragma unroll
            for (int q = 0; q < 8; q++) tot += sf[q];
            double lstd = (double)(tot / 126.f);
            out[0] = (float)(g_div_sum * (1.0e9 / 8193150.0));
            out[1] = (float)(g_smooth_sum * (10.0 / 7870952.0) + lstd * 100.0);
        }
    }
}

__global__ void kZ_zero() {
    int t = threadIdx.x;
    if (t == 0) { g_div_sum = 0.0; g_smooth_sum = 0.0; g_done = 0u; }
    if (t < 126) { ((float*)g_sbin)[t] = 0.f; ((float*)g_qbin)[t] = 0.f; }
}

extern "C" void kernel_launch(void* const* d_in, const int* in_sizes, int n_in,
                              void* d_out, int out_size) {
    const float* outp = (const float*)d_in[0];
    const float* tgt  = (const float*)d_in[1];
    if (n_in >= 2 && in_sizes[0] > in_sizes[1]) {
        const float* tmp = outp; outp = tgt; tgt = tmp;
    }
    float* out = (float*)d_out;

    kZ_zero<<<1, 128>>>();
    kFused<<<NBLK, 256>>>(outp, tgt, out);
}